// round 2
// baseline (speedup 1.0000x reference)
#include <cuda_runtime.h>
#include <cstdint>

// Problem shapes (fixed per reference setup_inputs)
#define BT   4096
#define HDIM 2048
#define VDIM 32000

// Output layout: [loss(1) | logits(BT*V) | lse(BT) | ntl(BT) | grad_x(BT*H)]
#define OUT_LOSS   0
#define OUT_LOGITS 1LL
#define OUT_LSE    (1LL + (long long)BT * VDIM)
#define OUT_NTL    (OUT_LSE + BT)
#define OUT_GRADX  (OUT_NTL + BT)

// GEMM tiling
#define BM 128
#define BN 128
#define BK 32
#define AS_STRIDE 36   // [rows][36] pad -> conflict-free fragment LDS
#define BS_STRIDE 136  // [k][136]  pad -> conflict-free

__device__ __forceinline__ uint32_t f2tf(float x) {
    uint32_t r;
    asm("cvt.rna.tf32.f32 %0, %1;" : "=r"(r) : "f"(x));
    return r;
}

__device__ __forceinline__ void mma8(float* d, const uint32_t* a, const uint32_t* b) {
    asm volatile(
        "mma.sync.aligned.m16n8k8.row.col.f32.tf32.tf32.f32 "
        "{%0,%1,%2,%3}, {%4,%5,%6,%7}, {%8,%9}, {%0,%1,%2,%3};\n"
        : "+f"(d[0]), "+f"(d[1]), "+f"(d[2]), "+f"(d[3])
        : "r"(a[0]), "r"(a[1]), "r"(a[2]), "r"(a[3]),
          "r"(b[0]), "r"(b[1]));
}

// ---------------------------------------------------------------------------
// Phase 1: logits = x @ w^T   (A = x [BT,H] row-major, B = w [V,H] row-major)
// ---------------------------------------------------------------------------
__global__ __launch_bounds__(256, 2) void gemm1_kernel(
    const float* __restrict__ x, const float* __restrict__ w,
    float* __restrict__ out)
{
    __shared__ uint32_t As[BM][AS_STRIDE];  // x tile   [m][k]
    __shared__ uint32_t Bs[BN][AS_STRIDE];  // w tile   [n][k]

    const int tid  = threadIdx.x;
    const int lane = tid & 31;
    const int wid  = tid >> 5;
    const int g    = lane >> 2;   // groupID
    const int tg   = lane & 3;    // threadID_in_group
    const int wm   = wid & 3;     // 4 warps along M
    const int wn   = wid >> 2;    // 2 warps along N
    const int m0   = blockIdx.x * BM;
    const int n0   = blockIdx.y * BN;

    float acc[2][8][4];
    #pragma unroll
    for (int i = 0; i < 2; i++)
        #pragma unroll
        for (int j = 0; j < 8; j++)
            #pragma unroll
            for (int q = 0; q < 4; q++) acc[i][j][q] = 0.f;

    float pa[16], pb[16];
    #pragma unroll
    for (int i = 0; i < 16; i++) {
        int e = tid + i * 256;
        int r = e >> 5, c = e & 31;
        pa[i] = x[(size_t)(m0 + r) * HDIM + c];
        pb[i] = w[(size_t)(n0 + r) * HDIM + c];
    }

    for (int k0 = 0; k0 < HDIM; k0 += BK) {
        __syncthreads();
        #pragma unroll
        for (int i = 0; i < 16; i++) {
            int e = tid + i * 256;
            int r = e >> 5, c = e & 31;
            As[r][c] = f2tf(pa[i]);
            Bs[r][c] = f2tf(pb[i]);
        }
        __syncthreads();

        if (k0 + BK < HDIM) {
            #pragma unroll
            for (int i = 0; i < 16; i++) {
                int e = tid + i * 256;
                int r = e >> 5, c = e & 31;
                pa[i] = x[(size_t)(m0 + r) * HDIM + k0 + BK + c];
                pb[i] = w[(size_t)(n0 + r) * HDIM + k0 + BK + c];
            }
        }

        #pragma unroll
        for (int kk = 0; kk < BK; kk += 8) {
            uint32_t af[2][4];
            #pragma unroll
            for (int mt = 0; mt < 2; mt++) {
                int mr = wm * 32 + mt * 16;
                af[mt][0] = As[mr + g][kk + tg];
                af[mt][1] = As[mr + g + 8][kk + tg];
                af[mt][2] = As[mr + g][kk + tg + 4];
                af[mt][3] = As[mr + g + 8][kk + tg + 4];
            }
            #pragma unroll
            for (int nt = 0; nt < 8; nt++) {
                int nr = wn * 64 + nt * 8;
                uint32_t bf[2];
                bf[0] = Bs[nr + g][kk + tg];       // B[k][n] = w[n][k]
                bf[1] = Bs[nr + g][kk + tg + 4];
                mma8(acc[0][nt], af[0], bf);
                mma8(acc[1][nt], af[1], bf);
            }
        }
    }

    float* outL = out + OUT_LOGITS;
    #pragma unroll
    for (int mt = 0; mt < 2; mt++) {
        #pragma unroll
        for (int nt = 0; nt < 8; nt++) {
            int r = m0 + wm * 32 + mt * 16 + g;
            int c = n0 + wn * 64 + nt * 8 + tg * 2;
            outL[(size_t)r * VDIM + c]           = acc[mt][nt][0];
            outL[(size_t)r * VDIM + c + 1]       = acc[mt][nt][1];
            outL[(size_t)(r + 8) * VDIM + c]     = acc[mt][nt][2];
            outL[(size_t)(r + 8) * VDIM + c + 1] = acc[mt][nt][3];
        }
    }
}

// ---------------------------------------------------------------------------
// Phase 2: per-row max + sumexp -> lse ; neg_target_logits
// Target dtype is detected at runtime: JAX without x64 silently downcasts
// int64 -> int32. Safe detection: read odd int32 words (always in-bounds for
// both layouts over [0,4096)); all-zero => little-endian int64 (values<32000),
// nonzero => int32.
// ---------------------------------------------------------------------------
__global__ void rowstat_kernel(const void* __restrict__ target,
                               float* __restrict__ out)
{
    __shared__ float red[256];
    __shared__ int oddor;
    const int row = blockIdx.x;
    const int tid = threadIdx.x;
    const float* lr = out + OUT_LOGITS + (size_t)row * VDIM;

    // --- target dtype detection (cheap, L2-resident) ---
    if (tid == 0) oddor = 0;
    __syncthreads();
    {
        const int* t32 = (const int*)target;
        int f = 0;
        for (int i = tid; i < BT / 2; i += 256) f |= t32[2 * i + 1];
        if (f) atomicOr(&oddor, 1);
    }

    float m = -1e30f;
    for (int v = tid; v < VDIM; v += 256) m = fmaxf(m, lr[v]);
    red[tid] = m;
    __syncthreads();
    for (int s = 128; s > 0; s >>= 1) {
        if (tid < s) red[tid] = fmaxf(red[tid], red[tid + s]);
        __syncthreads();
    }
    const float rmax = red[0];
    __syncthreads();

    float s = 0.f;
    for (int v = tid; v < VDIM; v += 256) s += __expf(lr[v] - rmax);
    red[tid] = s;
    __syncthreads();
    for (int st = 128; st > 0; st >>= 1) {
        if (tid < st) red[tid] += red[tid + st];
        __syncthreads();
    }

    if (tid == 0) {
        out[OUT_LSE + row] = rmax + logf(red[0]);
        long long t;
        if (oddor) {
            t = (long long)((const int*)target)[row];          // int32 targets
        } else {
            t = ((const long long*)target)[row];               // true int64
        }
        if (t < 0) t = 0;
        if (t >= VDIM) t = VDIM - 1;
        out[OUT_NTL + row] = -lr[t];
    }
}

// ---------------------------------------------------------------------------
// Phase 3: loss = mean(ntl + lse)
// ---------------------------------------------------------------------------
__global__ void loss_kernel(float* __restrict__ out)
{
    __shared__ float red[256];
    const int tid = threadIdx.x;
    float s = 0.f;
    for (int i = tid; i < BT; i += 256)
        s += out[OUT_LSE + i] + out[OUT_NTL + i];
    red[tid] = s;
    __syncthreads();
    for (int st = 128; st > 0; st >>= 1) {
        if (tid < st) red[tid] += red[tid + st];
        __syncthreads();
    }
    if (tid == 0) out[OUT_LOSS] = red[0] / (float)BT;
}

// ---------------------------------------------------------------------------
// Phase 4: grad_x = exp(logits - lse) @ w
// ---------------------------------------------------------------------------
__global__ __launch_bounds__(256, 2) void gemm2_kernel(
    const float* __restrict__ w, float* __restrict__ out)
{
    __shared__ uint32_t As[BM][AS_STRIDE];   // probs tile [m][k]
    __shared__ uint32_t Bs[BK][BS_STRIDE];   // w tile     [k][n]
    __shared__ float lses[BM];

    const int tid  = threadIdx.x;
    const int lane = tid & 31;
    const int wid  = tid >> 5;
    const int g    = lane >> 2;
    const int tg   = lane & 3;
    const int wm   = wid & 3;
    const int wn   = wid >> 2;
    const int n0   = blockIdx.x * BN;
    const int m0   = blockIdx.y * BM;

    if (tid < BM) lses[tid] = out[OUT_LSE + m0 + tid];

    float acc[2][8][4];
    #pragma unroll
    for (int i = 0; i < 2; i++)
        #pragma unroll
        for (int j = 0; j < 8; j++)
            #pragma unroll
            for (int q = 0; q < 4; q++) acc[i][j][q] = 0.f;

    const float* outL = out + OUT_LOGITS;

    float pa[16], pb[16];
    #pragma unroll
    for (int i = 0; i < 16; i++) {
        int e = tid + i * 256;
        int ra = e >> 5, ca = e & 31;        // A: [m][k] 128x32
        int rb = e >> 7, cb = e & 127;       // B: [k][n]  32x128
        pa[i] = outL[(size_t)(m0 + ra) * VDIM + ca];
        pb[i] = w[(size_t)rb * HDIM + n0 + cb];
    }

    for (int k0 = 0; k0 < VDIM; k0 += BK) {
        __syncthreads();
        #pragma unroll
        for (int i = 0; i < 16; i++) {
            int e = tid + i * 256;
            int ra = e >> 5, ca = e & 31;
            int rb = e >> 7, cb = e & 127;
            As[ra][ca] = f2tf(__expf(pa[i] - lses[ra]));
            Bs[rb][cb] = f2tf(pb[i]);
        }
        __syncthreads();

        if (k0 + BK < VDIM) {
            #pragma unroll
            for (int i = 0; i < 16; i++) {
                int e = tid + i * 256;
                int ra = e >> 5, ca = e & 31;
                int rb = e >> 7, cb = e & 127;
                pa[i] = outL[(size_t)(m0 + ra) * VDIM + k0 + BK + ca];
                pb[i] = w[(size_t)(k0 + BK + rb) * HDIM + n0 + cb];
            }
        }

        #pragma unroll
        for (int kk = 0; kk < BK; kk += 8) {
            uint32_t af[2][4];
            #pragma unroll
            for (int mt = 0; mt < 2; mt++) {
                int mr = wm * 32 + mt * 16;
                af[mt][0] = As[mr + g][kk + tg];
                af[mt][1] = As[mr + g + 8][kk + tg];
                af[mt][2] = As[mr + g][kk + tg + 4];
                af[mt][3] = As[mr + g + 8][kk + tg + 4];
            }
            #pragma unroll
            for (int nt = 0; nt < 8; nt++) {
                int nr = wn * 64 + nt * 8;
                uint32_t bf[2];
                bf[0] = Bs[kk + tg][nr + g];       // B[k][n] = w[k][n]
                bf[1] = Bs[kk + tg + 4][nr + g];
                mma8(acc[0][nt], af[0], bf);
                mma8(acc[1][nt], af[1], bf);
            }
        }
    }

    float* outG = out + OUT_GRADX;
    #pragma unroll
    for (int mt = 0; mt < 2; mt++) {
        #pragma unroll
        for (int nt = 0; nt < 8; nt++) {
            int r = m0 + wm * 32 + mt * 16 + g;
            int c = n0 + wn * 64 + nt * 8 + tg * 2;
            outG[(size_t)r * HDIM + c]           = acc[mt][nt][0];
            outG[(size_t)r * HDIM + c + 1]       = acc[mt][nt][1];
            outG[(size_t)(r + 8) * HDIM + c]     = acc[mt][nt][2];
            outG[(size_t)(r + 8) * HDIM + c + 1] = acc[mt][nt][3];
        }
    }
}

// ---------------------------------------------------------------------------
extern "C" void kernel_launch(void* const* d_in, const int* in_sizes, int n_in,
                              void* d_out, int out_size)
{
    const float* x   = (const float*)d_in[0];
    const float* w   = (const float*)d_in[1];
    const void*  tgt = d_in[2];
    float*       out = (float*)d_out;

    dim3 g1(BT / BM, VDIM / BN);   // (32, 250), m fastest -> A stays in L2
    gemm1_kernel<<<g1, 256>>>(x, w, out);

    rowstat_kernel<<<BT, 256>>>(tgt, out);
    loss_kernel<<<1, 256>>>(out);

    dim3 g2(HDIM / BN, BT / BM);   // (16, 32), n fastest -> B panels resident
    gemm2_kernel<<<g2, 256>>>(w, out);
}

// round 3
// speedup vs baseline: 1.8413x; 1.8413x over previous
#include <cuda_runtime.h>
#include <cstdint>

#define BT   4096
#define HDIM 2048
#define VDIM 32000

// Output layout: [loss(1) | logits(BT*V) | lse(BT) | ntl(BT) | grad_x(BT*H)]
#define OUT_LOSS   0
#define OUT_LOGITS 1LL
#define OUT_LSE    (1LL + (long long)BT * VDIM)
#define OUT_NTL    (OUT_LSE + BT)
#define OUT_GRADX  (OUT_NTL + BT)

#define BM 128
#define BN 128
#define BK 32

// ---- scratch (allowed: __device__ globals) ----
__device__ uint32_t g_wt[(size_t)VDIM * HDIM];     // tf32(w)      262 MB
__device__ uint32_t g_xt[(size_t)BT * HDIM];       // tf32(x)       33 MB
__device__ uint32_t g_probs[(size_t)BT * VDIM];    // tf32(exp(l-max)) 524 MB
__device__ float    g_scale[BT];                   // 1/Z per row

__device__ __forceinline__ uint32_t f2tf(float x) {
    uint32_t r;
    asm("cvt.rna.tf32.f32 %0, %1;" : "=r"(r) : "f"(x));
    return r;
}

__device__ __forceinline__ void mma8(float* d, const uint32_t* a, const uint32_t* b) {
    asm volatile(
        "mma.sync.aligned.m16n8k8.row.col.f32.tf32.tf32.f32 "
        "{%0,%1,%2,%3}, {%4,%5,%6,%7}, {%8,%9}, {%0,%1,%2,%3};\n"
        : "+f"(d[0]), "+f"(d[1]), "+f"(d[2]), "+f"(d[3])
        : "r"(a[0]), "r"(a[1]), "r"(a[2]), "r"(a[3]),
          "r"(b[0]), "r"(b[1]));
}

__device__ __forceinline__ void cpa16(uint32_t smem, const void* gmem) {
    asm volatile("cp.async.cg.shared.global [%0], [%1], 16;\n"
                 :: "r"(smem), "l"(gmem));
}
__device__ __forceinline__ void cpa_commit() {
    asm volatile("cp.async.commit_group;\n" ::: "memory");
}
__device__ __forceinline__ void cpa_wait0() {
    asm volatile("cp.async.wait_group 0;\n" ::: "memory");
}

// ---------------------------------------------------------------------------
// Phase 0: convert x and w to tf32 (RNA, zero-mean rounding)
// ---------------------------------------------------------------------------
__global__ void convert_kernel(const float* __restrict__ x,
                               const float* __restrict__ w)
{
    const size_t N1 = (size_t)BT * HDIM / 4;
    const size_t N2 = (size_t)VDIM * HDIM / 4;
    size_t i = (size_t)blockIdx.x * blockDim.x + threadIdx.x;
    const size_t stride = (size_t)gridDim.x * blockDim.x;
    for (; i < N1 + N2; i += stride) {
        if (i < N1) {
            float4 v = ((const float4*)x)[i];
            uint4 o = { f2tf(v.x), f2tf(v.y), f2tf(v.z), f2tf(v.w) };
            ((uint4*)g_xt)[i] = o;
        } else {
            float4 v = ((const float4*)w)[i - N1];
            uint4 o = { f2tf(v.x), f2tf(v.y), f2tf(v.z), f2tf(v.w) };
            ((uint4*)g_wt)[i - N1] = o;
        }
    }
}

// ---------------------------------------------------------------------------
// Phase 1: logits = x @ w^T  (A=g_xt [m][k], B=g_wt [n][k], both k-contig)
// 2-stage cp.async pipeline, smem-staged coalesced epilogue.
// ---------------------------------------------------------------------------
#define G1_AW (BM * 36)           // A stage words, stride 36
#define G1_BW (BN * 36)
#define G1_SW (G1_AW + G1_BW)     // 9216 words per stage
#define G1_SMEM (2 * G1_SW * 4)   // 73728 B

__global__ __launch_bounds__(256, 2) void gemm1_kernel(float* __restrict__ out)
{
    extern __shared__ uint32_t sm[];
    const uint32_t smb = (uint32_t)__cvta_generic_to_shared(sm);

    const int tid  = threadIdx.x;
    const int lane = tid & 31;
    const int wid  = tid >> 5;
    const int g    = lane >> 2;
    const int tg   = lane & 3;
    const int wm   = wid & 3;
    const int wn   = wid >> 2;
    const int m0   = blockIdx.x * BM;
    const int n0   = blockIdx.y * BN;

    // per-thread cp.async mapping: 4 chunks of 16B for each operand
    const int cr = tid >> 3;            // row 0..31 step (x8 chunks/row)
    const int cc = (tid & 7) * 4;       // col word 0,4,...,28

    float acc[2][8][4];
    #pragma unroll
    for (int i = 0; i < 2; i++)
        #pragma unroll
        for (int j = 0; j < 8; j++)
            #pragma unroll
            for (int q = 0; q < 4; q++) acc[i][j][q] = 0.f;

    auto issue = [&](int kt, int st) {
        const uint32_t sa = smb + (uint32_t)st * (G1_SW * 4);
        const uint32_t sbq = sa + G1_AW * 4;
        const int k0 = kt * BK;
        #pragma unroll
        for (int i = 0; i < 4; i++) {
            int r = cr + i * 32;
            cpa16(sa  + (r * 36 + cc) * 4, g_xt + (size_t)(m0 + r) * HDIM + k0 + cc);
            cpa16(sbq + (r * 36 + cc) * 4, g_wt + (size_t)(n0 + r) * HDIM + k0 + cc);
        }
        cpa_commit();
    };

    issue(0, 0);

    const int NK = HDIM / BK;   // 64
    for (int kt = 0; kt < NK; kt++) {
        cpa_wait0();
        __syncthreads();
        if (kt + 1 < NK) issue(kt + 1, (kt + 1) & 1);

        const uint32_t* A = sm + (kt & 1) * G1_SW;
        const uint32_t* B = A + G1_AW;
        #pragma unroll
        for (int kk = 0; kk < BK; kk += 8) {
            uint32_t af[2][4];
            #pragma unroll
            for (int mt = 0; mt < 2; mt++) {
                int mr = wm * 32 + mt * 16;
                af[mt][0] = A[(mr + g)     * 36 + kk + tg];
                af[mt][1] = A[(mr + g + 8) * 36 + kk + tg];
                af[mt][2] = A[(mr + g)     * 36 + kk + tg + 4];
                af[mt][3] = A[(mr + g + 8) * 36 + kk + tg + 4];
            }
            #pragma unroll
            for (int nt = 0; nt < 8; nt++) {
                int nr = wn * 64 + nt * 8;
                uint32_t bf[2];
                bf[0] = B[(nr + g) * 36 + kk + tg];
                bf[1] = B[(nr + g) * 36 + kk + tg + 4];
                mma8(acc[0][nt], af[0], bf);
                mma8(acc[1][nt], af[1], bf);
            }
        }
        __syncthreads();
    }

    // smem-staged epilogue (out+1 is 4B-aligned only -> coalesced STG.32)
    float* sf = (float*)sm;             // 128 x 132 floats = 67584 B
    #pragma unroll
    for (int mt = 0; mt < 2; mt++) {
        #pragma unroll
        for (int nt = 0; nt < 8; nt++) {
            int r = wm * 32 + mt * 16 + g;
            int c = wn * 64 + nt * 8 + tg * 2;
            sf[r * 132 + c]           = acc[mt][nt][0];
            sf[r * 132 + c + 1]       = acc[mt][nt][1];
            sf[(r + 8) * 132 + c]     = acc[mt][nt][2];
            sf[(r + 8) * 132 + c + 1] = acc[mt][nt][3];
        }
    }
    __syncthreads();
    float* outL = out + OUT_LOGITS;
    #pragma unroll
    for (int i = 0; i < 64; i++) {
        int e = tid + i * 256;
        int r = e >> 7, c = e & 127;
        outL[(size_t)(m0 + r) * VDIM + n0 + c] = sf[r * 132 + c];
    }
}

// ---------------------------------------------------------------------------
// Phase 2: fused rowstat + E-matrix: rowmax, Z=sum exp, lse, ntl,
//          g_probs = tf32(exp(l - rowmax)), g_scale = 1/Z.
// Target dtype runtime-detected (JAX x64-off downcasts int64->int32).
// ---------------------------------------------------------------------------
__global__ void softmax_kernel(const void* __restrict__ target,
                               float* __restrict__ out)
{
    __shared__ float red[256];
    __shared__ int oddor;
    const int row = blockIdx.x;
    const int tid = threadIdx.x;
    const float* lr = out + OUT_LOGITS + (size_t)row * VDIM;

    if (tid == 0) oddor = 0;
    __syncthreads();
    {
        const int* t32 = (const int*)target;
        int f = 0;
        for (int i = tid; i < BT / 2; i += 256) f |= t32[2 * i + 1];
        if (f) atomicOr(&oddor, 1);
    }

    float m = -1e30f;
    for (int v = tid; v < VDIM; v += 256) m = fmaxf(m, lr[v]);
    red[tid] = m;
    __syncthreads();
    for (int s = 128; s > 0; s >>= 1) {
        if (tid < s) red[tid] = fmaxf(red[tid], red[tid + s]);
        __syncthreads();
    }
    const float rmax = red[0];
    __syncthreads();

    uint32_t* pr = g_probs + (size_t)row * VDIM;
    float s = 0.f;
    for (int v = tid; v < VDIM; v += 256) {
        float e = __expf(lr[v] - rmax);
        s += e;
        pr[v] = f2tf(e);
    }
    red[tid] = s;
    __syncthreads();
    for (int st = 128; st > 0; st >>= 1) {
        if (tid < st) red[tid] += red[tid + st];
        __syncthreads();
    }

    if (tid == 0) {
        float Z = red[0];
        out[OUT_LSE + row] = rmax + logf(Z);
        g_scale[row] = 1.0f / Z;
        long long t;
        if (oddor) t = (long long)((const int*)target)[row];
        else       t = ((const long long*)target)[row];
        if (t < 0) t = 0;
        if (t >= VDIM) t = VDIM - 1;
        out[OUT_NTL + row] = -lr[t];
    }
}

// ---------------------------------------------------------------------------
// Phase 3: loss = mean(ntl + lse)
// ---------------------------------------------------------------------------
__global__ void loss_kernel(float* __restrict__ out)
{
    __shared__ float red[256];
    const int tid = threadIdx.x;
    float s = 0.f;
    for (int i = tid; i < BT; i += 256)
        s += out[OUT_LSE + i] + out[OUT_NTL + i];
    red[tid] = s;
    __syncthreads();
    for (int st = 128; st > 0; st >>= 1) {
        if (tid < st) red[tid] += red[tid + st];
        __syncthreads();
    }
    if (tid == 0) out[OUT_LOSS] = red[0] / (float)BT;
}

// ---------------------------------------------------------------------------
// Phase 4: grad_x = diag(1/Z) * E @ w   (A=g_probs [m][k], B=g_wt [k=v][n=h])
// ---------------------------------------------------------------------------
#define G2_AW (BM * 36)           // A stage words, stride 36
#define G2_BW (BK * 136)          // B stage words, stride 136 (n-contig)
#define G2_SW (G2_AW + G2_BW)     // 8960 words
#define G2_SMEM (2 * G2_SW * 4)   // 71680 B

__global__ __launch_bounds__(256, 2) void gemm2_kernel(float* __restrict__ out)
{
    extern __shared__ uint32_t sm[];
    const uint32_t smb = (uint32_t)__cvta_generic_to_shared(sm);

    const int tid  = threadIdx.x;
    const int lane = tid & 31;
    const int wid  = tid >> 5;
    const int g    = lane >> 2;
    const int tg   = lane & 3;
    const int wm   = wid & 3;
    const int wn   = wid >> 2;
    const int n0   = blockIdx.x * BN;
    const int m0   = blockIdx.y * BM;

    const int acr = tid >> 3;             // A rows: x8 chunks per 32-wide row
    const int acc_ = (tid & 7) * 4;
    const int brk = tid >> 5;             // B rows: x32 chunks per 128-wide row
    const int bcc = (tid & 31) * 4;

    float acc[2][8][4];
    #pragma unroll
    for (int i = 0; i < 2; i++)
        #pragma unroll
        for (int j = 0; j < 8; j++)
            #pragma unroll
            for (int q = 0; q < 4; q++) acc[i][j][q] = 0.f;

    auto issue = [&](int kt, int st) {
        const uint32_t sa = smb + (uint32_t)st * (G2_SW * 4);
        const uint32_t sbq = sa + G2_AW * 4;
        const int k0 = kt * BK;
        #pragma unroll
        for (int i = 0; i < 4; i++) {
            int r = acr + i * 32;
            cpa16(sa + (r * 36 + acc_) * 4,
                  g_probs + (size_t)(m0 + r) * VDIM + k0 + acc_);
            int rk = brk + i * 8;
            cpa16(sbq + (rk * 136 + bcc) * 4,
                  g_wt + (size_t)(k0 + rk) * HDIM + n0 + bcc);
        }
        cpa_commit();
    };

    issue(0, 0);

    const int NK = VDIM / BK;   // 1000
    for (int kt = 0; kt < NK; kt++) {
        cpa_wait0();
        __syncthreads();
        if (kt + 1 < NK) issue(kt + 1, (kt + 1) & 1);

        const uint32_t* A = sm + (kt & 1) * G2_SW;
        const uint32_t* B = A + G2_AW;
        #pragma unroll
        for (int kk = 0; kk < BK; kk += 8) {
            uint32_t af[2][4];
            #pragma unroll
            for (int mt = 0; mt < 2; mt++) {
                int mr = wm * 32 + mt * 16;
                af[mt][0] = A[(mr + g)     * 36 + kk + tg];
                af[mt][1] = A[(mr + g + 8) * 36 + kk + tg];
                af[mt][2] = A[(mr + g)     * 36 + kk + tg + 4];
                af[mt][3] = A[(mr + g + 8) * 36 + kk + tg + 4];
            }
            #pragma unroll
            for (int nt = 0; nt < 8; nt++) {
                int nr = wn * 64 + nt * 8;
                uint32_t bf[2];
                bf[0] = B[(kk + tg)     * 136 + nr + g];
                bf[1] = B[(kk + tg + 4) * 136 + nr + g];
                mma8(acc[0][nt], af[0], bf);
                mma8(acc[1][nt], af[1], bf);
            }
        }
        __syncthreads();
    }

    float* sf = (float*)sm;
    #pragma unroll
    for (int mt = 0; mt < 2; mt++) {
        #pragma unroll
        for (int nt = 0; nt < 8; nt++) {
            int r = wm * 32 + mt * 16 + g;
            int c = wn * 64 + nt * 8 + tg * 2;
            sf[r * 132 + c]           = acc[mt][nt][0];
            sf[r * 132 + c + 1]       = acc[mt][nt][1];
            sf[(r + 8) * 132 + c]     = acc[mt][nt][2];
            sf[(r + 8) * 132 + c + 1] = acc[mt][nt][3];
        }
    }
    __syncthreads();
    float* outG = out + OUT_GRADX;
    #pragma unroll
    for (int i = 0; i < 64; i++) {
        int e = tid + i * 256;
        int r = e >> 7, c = e & 127;
        float sc = g_scale[m0 + r];   // uniform per warp, L1/L2 cached
        outG[(size_t)(m0 + r) * HDIM + n0 + c] = sf[r * 132 + c] * sc;
    }
}

// ---------------------------------------------------------------------------
extern "C" void kernel_launch(void* const* d_in, const int* in_sizes, int n_in,
                              void* d_out, int out_size)
{
    const float* x   = (const float*)d_in[0];
    const float* w   = (const float*)d_in[1];
    const void*  tgt = d_in[2];
    float*       out = (float*)d_out;

    cudaFuncSetAttribute(gemm1_kernel,
        cudaFuncAttributeMaxDynamicSharedMemorySize, G1_SMEM);
    cudaFuncSetAttribute(gemm2_kernel,
        cudaFuncAttributeMaxDynamicSharedMemorySize, G2_SMEM);

    convert_kernel<<<2048, 256>>>(x, w);

    dim3 g1(BT / BM, VDIM / BN);   // (32, 250), m fastest -> x panels L2-resident
    gemm1_kernel<<<g1, 256, G1_SMEM>>>(out);

    softmax_kernel<<<BT, 256>>>(tgt, out);
    loss_kernel<<<1, 256>>>(out);

    dim3 g2(HDIM / BN, BT / BM);   // (16, 32), n fastest -> probs panels L2-resident
    gemm2_kernel<<<g2, 256, G2_SMEM>>>(out);
}

// round 5
// speedup vs baseline: 1.9479x; 1.0579x over previous
#include <cuda_runtime.h>
#include <cstdint>

#define BT   4096
#define HDIM 2048
#define VDIM 32000
#define NT1  (VDIM / 128)          // 250 gemm1 n-tiles

// Output layout: [loss(1) | logits(BT*V) | lse(BT) | ntl(BT) | grad_x(BT*H)]
#define OUT_LOSS   0
#define OUT_LOGITS 1LL
#define OUT_LSE    (1LL + (long long)BT * VDIM)
#define OUT_NTL    (OUT_LSE + BT)
#define OUT_GRADX  (OUT_NTL + BT)

#define BM 128
#define BN 128
#define BK 32

// gemm1 stage: A[128][36] + B[128][36] words
#define G1_AW 4608
#define G1_SW 9216
#define G1_SMEM (3 * G1_SW * 4)     // 110592 B
// gemm2 stage: A[128][36] + B[32][136] words
#define G2_AW 4608
#define G2_SW 8960
#define G2_SMEM (3 * G2_SW * 4)     // 107520 B

// ---- scratch (__device__ globals allowed) ----
__device__ uint32_t g_wt [(size_t)VDIM * HDIM];   // tf32(w) [v][h]
__device__ uint32_t g_xt [(size_t)BT * HDIM];     // tf32(x)
__device__ uint32_t g_probs[(size_t)BT * VDIM];   // tf32(exp(logit))
__device__ float    g_zpart[(size_t)NT1 * BT];    // per-tile row sums of exp
__device__ float    g_scale[BT];                  // 1/Z

__device__ __forceinline__ uint32_t f2tf(float x) {
    uint32_t r;
    asm("cvt.rna.tf32.f32 %0, %1;" : "=r"(r) : "f"(x));
    return r;
}
__device__ __forceinline__ void mma8(float* d, const uint32_t* a, const uint32_t* b) {
    asm volatile(
        "mma.sync.aligned.m16n8k8.row.col.f32.tf32.tf32.f32 "
        "{%0,%1,%2,%3}, {%4,%5,%6,%7}, {%8,%9}, {%0,%1,%2,%3};\n"
        : "+f"(d[0]), "+f"(d[1]), "+f"(d[2]), "+f"(d[3])
        : "r"(a[0]), "r"(a[1]), "r"(a[2]), "r"(a[3]),
          "r"(b[0]), "r"(b[1]));
}
__device__ __forceinline__ void cpa16(uint32_t smem, const void* gmem) {
    asm volatile("cp.async.cg.shared.global [%0], [%1], 16;\n" :: "r"(smem), "l"(gmem));
}
__device__ __forceinline__ void cpa_commit() {
    asm volatile("cp.async.commit_group;\n" ::: "memory");
}
__device__ __forceinline__ void cpa_wait0() {
    asm volatile("cp.async.wait_group 0;\n" ::: "memory");
}
__device__ __forceinline__ void cpa_wait1() {
    asm volatile("cp.async.wait_group 1;\n" ::: "memory");
}

// ---------------------------------------------------------------------------
// Phase 0: tf32 pre-convert (RNA, zero-mean rounding)
// ---------------------------------------------------------------------------
__global__ void convert_kernel(const float* __restrict__ x,
                               const float* __restrict__ w)
{
    const size_t N1 = (size_t)BT * HDIM / 4;
    const size_t N2 = (size_t)VDIM * HDIM / 4;
    size_t i = (size_t)blockIdx.x * blockDim.x + threadIdx.x;
    const size_t stride = (size_t)gridDim.x * blockDim.x;
    for (; i < N1 + N2; i += stride) {
        if (i < N1) {
            float4 v = ((const float4*)x)[i];
            uint4 o = { f2tf(v.x), f2tf(v.y), f2tf(v.z), f2tf(v.w) };
            ((uint4*)g_xt)[i] = o;
        } else {
            float4 v = ((const float4*)w)[i - N1];
            uint4 o = { f2tf(v.x), f2tf(v.y), f2tf(v.z), f2tf(v.w) };
            ((uint4*)g_wt)[i - N1] = o;
        }
    }
}

// ---------------------------------------------------------------------------
// GEMM core: 128 threads, 4 warps (2m x 2n), warp tile 64x64, 3-stage cp.async
// ---------------------------------------------------------------------------
#define GEMM_DECLS                                            \
    const int tid  = threadIdx.x;                             \
    const int lane = tid & 31;                                \
    const int wid  = tid >> 5;                                \
    const int g    = lane >> 2;                               \
    const int tg   = lane & 3;                                \
    const int wm   = wid & 1;                                 \
    const int wn   = wid >> 1;                                \
    float acc[4][8][4];                                       \
    _Pragma("unroll")                                         \
    for (int i = 0; i < 4; i++)                               \
        _Pragma("unroll")                                     \
        for (int j = 0; j < 8; j++)                           \
            _Pragma("unroll")                                 \
            for (int q = 0; q < 4; q++) acc[i][j][q] = 0.f;

#define GEMM_COMPUTE(A, B, BSTRIDE, BROWMAJ)                  \
    _Pragma("unroll")                                         \
    for (int kk = 0; kk < BK; kk += 8) {                      \
        uint32_t af[4][4];                                    \
        _Pragma("unroll")                                     \
        for (int mt = 0; mt < 4; mt++) {                      \
            int mr = wm * 64 + mt * 16;                       \
            af[mt][0] = A[(mr + g)     * 36 + kk + tg];       \
            af[mt][1] = A[(mr + g + 8) * 36 + kk + tg];       \
            af[mt][2] = A[(mr + g)     * 36 + kk + tg + 4];   \
            af[mt][3] = A[(mr + g + 8) * 36 + kk + tg + 4];   \
        }                                                     \
        _Pragma("unroll")                                     \
        for (int nt = 0; nt < 8; nt++) {                      \
            int nr = wn * 64 + nt * 8;                        \
            uint32_t bf[2];                                   \
            if (BROWMAJ) {                                    \
                bf[0] = B[(nr + g) * 36 + kk + tg];           \
                bf[1] = B[(nr + g) * 36 + kk + tg + 4];       \
            } else {                                          \
                bf[0] = B[(kk + tg)     * 136 + nr + g];      \
                bf[1] = B[(kk + tg + 4) * 136 + nr + g];      \
            }                                                 \
            _Pragma("unroll")                                 \
            for (int mt = 0; mt < 4; mt++)                    \
                mma8(acc[mt][nt], af[mt], bf);                \
        }                                                     \
    }

// ---------------------------------------------------------------------------
// Phase 1: logits = x @ w^T ; epilogue also emits probs=tf32(exp(l)) and
// per-tile row sums of exp into g_zpart[ntile][row].
// ---------------------------------------------------------------------------
__global__ __launch_bounds__(128, 2) void gemm1_kernel(float* __restrict__ out)
{
    extern __shared__ uint32_t sm[];
    const uint32_t smb = (uint32_t)__cvta_generic_to_shared(sm);
    GEMM_DECLS
    const int m0 = blockIdx.x * BM;
    const int n0 = blockIdx.y * BN;

    auto issue = [&](int kt) {
        const uint32_t sb = smb + (uint32_t)(kt % 3) * (G1_SW * 4);
        const int k0 = kt * BK;
        #pragma unroll
        for (int i = 0; i < 8; i++) {
            int idx = tid + i * 128;
            int r = idx >> 3, cw = (idx & 7) * 4;
            cpa16(sb + (r * 36 + cw) * 4, g_xt + (size_t)(m0 + r) * HDIM + k0 + cw);
        }
        #pragma unroll
        for (int i = 0; i < 8; i++) {
            int idx = tid + i * 128;
            int r = idx >> 3, cw = (idx & 7) * 4;
            cpa16(sb + (G1_AW + r * 36 + cw) * 4, g_wt + (size_t)(n0 + r) * HDIM + k0 + cw);
        }
        cpa_commit();
    };

    issue(0); issue(1);
    const int NK = HDIM / BK;   // 64
    for (int kt = 0; kt < NK; kt++) {
        if (kt + 1 < NK) cpa_wait1(); else cpa_wait0();
        __syncthreads();
        if (kt + 2 < NK) issue(kt + 2);
        const uint32_t* A = sm + (kt % 3) * G1_SW;
        const uint32_t* B = A + G1_AW;
        GEMM_COMPUTE(A, B, 36, 1)
    }

    // ---- epilogue: logits + probs + row exp-sums ----
    __syncthreads();
    float* sf = (float*)sm;                    // [128][132]
    float* rp = (float*)sm + 128 * 132;        // [128][4]
    #pragma unroll
    for (int mt = 0; mt < 4; mt++) {
        #pragma unroll
        for (int nt = 0; nt < 8; nt++) {
            int r = wm * 64 + mt * 16 + g;
            int c = wn * 64 + nt * 8 + tg * 2;
            sf[r * 132 + c]           = acc[mt][nt][0];
            sf[r * 132 + c + 1]       = acc[mt][nt][1];
            sf[(r + 8) * 132 + c]     = acc[mt][nt][2];
            sf[(r + 8) * 132 + c + 1] = acc[mt][nt][3];
        }
    }
    __syncthreads();

    float* outL = out + OUT_LOGITS;
    for (int i = 0; i < 128; i++) {
        float v = sf[i * 132 + tid];
        outL[(size_t)(m0 + i) * VDIM + n0 + tid] = v;
        float p = __expf(v);                   // |v| < ~1, no shift needed
        g_probs[(size_t)(m0 + i) * VDIM + n0 + tid] = f2tf(p);
        #pragma unroll
        for (int o = 16; o > 0; o >>= 1)
            p += __shfl_xor_sync(0xFFFFFFFFu, p, o);
        if (lane == 0) rp[i * 4 + wid] = p;
    }
    __syncthreads();
    {
        float z = rp[tid * 4 + 0] + rp[tid * 4 + 1] + rp[tid * 4 + 2] + rp[tid * 4 + 3];
        g_zpart[(size_t)blockIdx.y * BT + m0 + tid] = z;
    }
}

// ---------------------------------------------------------------------------
// Phase 2: zred — Z per row, lse, 1/Z, ntl. Target dtype runtime-detected.
// ---------------------------------------------------------------------------
__global__ void zred_kernel(const void* __restrict__ target,
                            float* __restrict__ out)
{
    __shared__ int oddor;
    const int tid = threadIdx.x;
    const int lane = tid & 31;
    const int wid = tid >> 5;
    const int row = blockIdx.x * 8 + wid;

    if (tid == 0) oddor = 0;
    __syncthreads();
    {
        const int* t32 = (const int*)target;
        int f = 0;
        for (int i = tid; i < BT / 2; i += 256) f |= t32[2 * i + 1];
        if (f) atomicOr(&oddor, 1);
    }
    __syncthreads();

    float s = 0.f;
    for (int t = lane; t < NT1; t += 32)
        s += g_zpart[(size_t)t * BT + row];
    #pragma unroll
    for (int o = 16; o > 0; o >>= 1)
        s += __shfl_xor_sync(0xFFFFFFFFu, s, o);

    if (lane == 0) {
        out[OUT_LSE + row] = logf(s);
        g_scale[row] = 1.0f / s;
        long long t;
        if (oddor) t = (long long)((const int*)target)[row];
        else       t = ((const long long*)target)[row];
        if (t < 0) t = 0;
        if (t >= VDIM) t = VDIM - 1;
        out[OUT_NTL + row] = -out[OUT_LOGITS + (size_t)row * VDIM + t];
    }
}

__global__ void loss_kernel(float* __restrict__ out)
{
    __shared__ float red[256];
    const int tid = threadIdx.x;
    float s = 0.f;
    for (int i = tid; i < BT; i += 256)
        s += out[OUT_LSE + i] + out[OUT_NTL + i];
    red[tid] = s;
    __syncthreads();
    for (int st = 128; st > 0; st >>= 1) {
        if (tid < st) red[tid] += red[tid + st];
        __syncthreads();
    }
    if (tid == 0) out[OUT_LOSS] = red[0] / (float)BT;
}

// ---------------------------------------------------------------------------
// Phase 3: grad_x = diag(1/Z) * E @ w   (A = g_probs [m][v], B = w [v][h])
// ---------------------------------------------------------------------------
__global__ __launch_bounds__(128, 2) void gemm2_kernel(float* __restrict__ out)
{
    extern __shared__ uint32_t sm[];
    const uint32_t smb = (uint32_t)__cvta_generic_to_shared(sm);
    GEMM_DECLS
    const int n0 = blockIdx.x * BN;
    const int m0 = blockIdx.y * BM;

    auto issue = [&](int kt) {
        const uint32_t sb = smb + (uint32_t)(kt % 3) * (G2_SW * 4);
        const int k0 = kt * BK;
        #pragma unroll
        for (int i = 0; i < 8; i++) {
            int idx = tid + i * 128;
            int r = idx >> 3, cw = (idx & 7) * 4;
            cpa16(sb + (r * 36 + cw) * 4, g_probs + (size_t)(m0 + r) * VDIM + k0 + cw);
        }
        #pragma unroll
        for (int i = 0; i < 8; i++) {
            int idx = tid + i * 128;
            int r = idx >> 5, cw = (idx & 31) * 4;
            cpa16(sb + (G2_AW + r * 136 + cw) * 4, g_wt + (size_t)(k0 + r) * HDIM + n0 + cw);
        }
        cpa_commit();
    };

    issue(0); issue(1);
    const int NK = VDIM / BK;   // 1000
    for (int kt = 0; kt < NK; kt++) {
        if (kt + 1 < NK) cpa_wait1(); else cpa_wait0();
        __syncthreads();
        if (kt + 2 < NK) issue(kt + 2);
        const uint32_t* A = sm + (kt % 3) * G2_SW;
        const uint32_t* B = A + G2_AW;
        GEMM_COMPUTE(A, B, 136, 0)
    }

    __syncthreads();
    float* sf = (float*)sm;
    #pragma unroll
    for (int mt = 0; mt < 4; mt++) {
        #pragma unroll
        for (int nt = 0; nt < 8; nt++) {
            int r = wm * 64 + mt * 16 + g;
            int c = wn * 64 + nt * 8 + tg * 2;
            sf[r * 132 + c]           = acc[mt][nt][0];
            sf[r * 132 + c + 1]       = acc[mt][nt][1];
            sf[(r + 8) * 132 + c]     = acc[mt][nt][2];
            sf[(r + 8) * 132 + c + 1] = acc[mt][nt][3];
        }
    }
    __syncthreads();
    float* outG = out + OUT_GRADX;
    for (int i = 0; i < 128; i++) {
        float v = sf[i * 132 + tid] * g_scale[m0 + i];
        outG[(size_t)(m0 + i) * HDIM + n0 + tid] = v;
    }
}

// ---------------------------------------------------------------------------
extern "C" void kernel_launch(void* const* d_in, const int* in_sizes, int n_in,
                              void* d_out, int out_size)
{
    const float* x   = (const float*)d_in[0];
    const float* w   = (const float*)d_in[1];
    const void*  tgt = d_in[2];
    float*       out = (float*)d_out;

    cudaFuncSetAttribute(gemm1_kernel,
        cudaFuncAttributeMaxDynamicSharedMemorySize, G1_SMEM);
    cudaFuncSetAttribute(gemm2_kernel,
        cudaFuncAttributeMaxDynamicSharedMemorySize, G2_SMEM);

    convert_kernel<<<2048, 256>>>(x, w);

    dim3 g1(BT / BM, VDIM / BN);   // (32, 250) m-fastest: x panels L2-resident
    gemm1_kernel<<<g1, 128, G1_SMEM>>>(out);

    zred_kernel<<<BT / 8, 256>>>(tgt, out);
    loss_kernel<<<1, 256>>>(out);

    dim3 g2(HDIM / BN, BT / BM);   // (16, 32) n-fastest: probs rows shared in L2
    gemm2_kernel<<<g2, 128, G2_SMEM>>>(out);
}

// round 6
// speedup vs baseline: 2.3741x; 1.2188x over previous
#include <cuda_runtime.h>
#include <cstdint>

#define BT   4096
#define HDIM 2048
#define VDIM 32000
#define NT1  (VDIM / 128)          // 250 gemm1 n-tiles
#define KC1  (HDIM / 8)            // 256 k-chunks gemm1
#define KC2  (VDIM / 8)            // 4000 k-chunks gemm2

// Output layout: [loss(1) | logits(BT*V) | lse(BT) | ntl(BT) | grad_x(BT*H)]
#define OUT_LOSS   0
#define OUT_LOGITS 1LL
#define OUT_LSE    (1LL + (long long)BT * VDIM)
#define OUT_NTL    (OUT_LSE + BT)
#define OUT_GRADX  (OUT_NTL + BT)

#define BM 128
#define BN 128
#define BK 32
// stage: A 8 m16-tiles * 512 words + B 16 n8-tiles * 256 words = 8192 words
#define STG_W  8192
#define G_SMEM (3 * STG_W * 4)     // 98304 B

// ---- scratch (__device__ globals allowed) ----
// Fragment-major layouts:
//   A-perm:  [m16][k8][lane][4] : j0=(g,tg) j1=(g+8,tg) j2=(g,tg+4) j3=(g+8,tg+4)
//   B-perm:  [n8][k8][lane][2]  : j0=(n=g,k=tg) j1=(n=g,k=tg+4)
__device__ uint32_t g_xt   [(size_t)(BT / 16) * KC1 * 128];   // x   A-perm
__device__ uint32_t g_wt   [(size_t)(VDIM / 8) * KC1 * 64];   // w   B-perm (n=v,k=h)
__device__ uint32_t g_wt2  [(size_t)(HDIM / 8) * KC2 * 64];   // w   B-perm (n=h,k=v)
__device__ uint32_t g_probs[(size_t)(BT / 16) * KC2 * 128];   // exp(logit) A-perm
__device__ float    g_zpart[(size_t)NT1 * BT];
__device__ float    g_scale[BT];

__device__ __forceinline__ uint32_t f2tf(float x) {
    uint32_t r;
    asm("cvt.rna.tf32.f32 %0, %1;" : "=r"(r) : "f"(x));
    return r;
}
__device__ __forceinline__ void mma8(float* d, const uint32_t* a, const uint32_t* b) {
    asm volatile(
        "mma.sync.aligned.m16n8k8.row.col.f32.tf32.tf32.f32 "
        "{%0,%1,%2,%3}, {%4,%5,%6,%7}, {%8,%9}, {%0,%1,%2,%3};\n"
        : "+f"(d[0]), "+f"(d[1]), "+f"(d[2]), "+f"(d[3])
        : "r"(a[0]), "r"(a[1]), "r"(a[2]), "r"(a[3]),
          "r"(b[0]), "r"(b[1]));
}
__device__ __forceinline__ void cpa16(uint32_t smem, const void* gmem) {
    asm volatile("cp.async.cg.shared.global [%0], [%1], 16;\n" :: "r"(smem), "l"(gmem));
}
__device__ __forceinline__ void cpa_commit() {
    asm volatile("cp.async.commit_group;\n" ::: "memory");
}
__device__ __forceinline__ void cpa_wait0() {
    asm volatile("cp.async.wait_group 0;\n" ::: "memory");
}
__device__ __forceinline__ void cpa_wait1() {
    asm volatile("cp.async.wait_group 1;\n" ::: "memory");
}

// ---------------------------------------------------------------------------
// Converters into fragment-major layouts
// ---------------------------------------------------------------------------
__global__ void convA_kernel(const float* __restrict__ x)   // x -> g_xt
{
    const int lane = threadIdx.x & 31;
    const int g = lane >> 2, tg = lane & 3;
    const int warp = (blockIdx.x * blockDim.x + threadIdx.x) >> 5;
    const int nwarp = (gridDim.x * blockDim.x) >> 5;
    const int NF = (BT / 16) * KC1;
    for (int f = warp; f < NF; f += nwarp) {
        int m16 = f >> 8, kc = f & (KC1 - 1);
        const float* p = x + (size_t)(m16 * 16 + g) * HDIM + kc * 8 + tg;
        uint4 o = { f2tf(p[0]), f2tf(p[8 * HDIM]), f2tf(p[4]), f2tf(p[8 * HDIM + 4]) };
        *(uint4*)(g_xt + (size_t)f * 128 + lane * 4) = o;
    }
}
__global__ void convB1_kernel(const float* __restrict__ w)  // w -> g_wt (n=v,k=h)
{
    const int lane = threadIdx.x & 31;
    const int g = lane >> 2, tg = lane & 3;
    const int warp = (blockIdx.x * blockDim.x + threadIdx.x) >> 5;
    const int nwarp = (gridDim.x * blockDim.x) >> 5;
    const int NF = (VDIM / 8) * KC1;
    for (int f = warp; f < NF; f += nwarp) {
        int v8 = f >> 8, kc = f & (KC1 - 1);
        const float* p = w + (size_t)(v8 * 8 + g) * HDIM + kc * 8 + tg;
        uint2 o = { f2tf(p[0]), f2tf(p[4]) };
        *(uint2*)(g_wt + (size_t)f * 64 + lane * 2) = o;
    }
}
__global__ void convB2_kernel(const float* __restrict__ w)  // w -> g_wt2 (n=h,k=v)
{
    const int lane = threadIdx.x & 31;
    const int g = lane >> 2, tg = lane & 3;
    const int warp = (blockIdx.x * blockDim.x + threadIdx.x) >> 5;
    const int nwarp = (gridDim.x * blockDim.x) >> 5;
    const int NF = (HDIM / 8) * KC2;
    for (int f = warp; f < NF; f += nwarp) {
        int h8 = f / KC2, vc = f - h8 * KC2;
        const float* p = w + (size_t)(vc * 8 + tg) * HDIM + h8 * 8 + g;
        uint2 o = { f2tf(p[0]), f2tf(p[4 * HDIM]) };
        *(uint2*)(g_wt2 + (size_t)f * 64 + lane * 2) = o;
    }
}

// ---------------------------------------------------------------------------
// GEMM core: 128 thr, 4 warps (2m x 2n), warp 64x64, 3-stage cp.async,
// LDS.128 A-fragments + LDS.64 B-fragments from fragment-major smem.
// ---------------------------------------------------------------------------
#define GEMM_DECLS                                            \
    const int tid  = threadIdx.x;                             \
    const int lane = tid & 31;                                \
    const int wid  = tid >> 5;                                \
    const int g    = lane >> 2;                               \
    const int tg   = lane & 3;                                \
    const int wm   = wid & 1;                                 \
    const int wn   = wid >> 1;                                \
    float acc[4][8][4];                                       \
    _Pragma("unroll")                                         \
    for (int i = 0; i < 4; i++)                               \
        _Pragma("unroll")                                     \
        for (int j = 0; j < 8; j++)                           \
            _Pragma("unroll")                                 \
            for (int q = 0; q < 4; q++) acc[i][j][q] = 0.f;

// stage issue: A frag-major [8 m16][4 kc][128w], B [16 n8][4 kc][64w]
#define GEMM_ISSUE(AG, BG, KCD)                                               \
    auto issue = [&](int kt) {                                                \
        const uint32_t sb = smb + (uint32_t)(kt % 3) * (STG_W * 4);           \
        const int kc0 = kt * 4;                                              \
        _Pragma("unroll")                                                     \
        for (int i = 0; i < 8; i++)                                           \
            cpa16(sb + i * 2048 + tid * 16,                                   \
                  AG + ((size_t)(m0 / 16 + i) * KCD + kc0) * 128 + tid * 4);  \
        _Pragma("unroll")                                                     \
        for (int i = 0; i < 8; i++) {                                         \
            int q = tid + i * 128;                                            \
            int n8 = q >> 6, off = q & 63;                                    \
            cpa16(sb + 16384 + q * 16,                                        \
                  BG + ((size_t)(n0 / 8 + n8) * KCD + kc0) * 64 + off * 4);   \
        }                                                                     \
        cpa_commit();                                                         \
    };

#define GEMM_COMPUTE(kt)                                                      \
    {                                                                         \
        const uint32_t* Aw = sm + (kt % 3) * STG_W;                           \
        const uint32_t* Bw = Aw + 4096;                                       \
        _Pragma("unroll")                                                     \
        for (int kc = 0; kc < 4; kc++) {                                      \
            uint4 av[4];                                                      \
            _Pragma("unroll")                                                 \
            for (int mt = 0; mt < 4; mt++)                                    \
                av[mt] = *(const uint4*)(Aw + (wm * 4 + mt) * 512 + kc * 128 + lane * 4); \
            _Pragma("unroll")                                                 \
            for (int nt = 0; nt < 8; nt++) {                                  \
                uint2 bv = *(const uint2*)(Bw + (wn * 8 + nt) * 256 + kc * 64 + lane * 2); \
                _Pragma("unroll")                                             \
                for (int mt = 0; mt < 4; mt++)                                \
                    mma8(acc[mt][nt], (const uint32_t*)&av[mt], (const uint32_t*)&bv); \
            }                                                                 \
        }                                                                     \
    }

// ---------------------------------------------------------------------------
// Phase 1: logits = x @ w^T; epilogue: logits, probs (A-perm), z partials
// ---------------------------------------------------------------------------
__global__ __launch_bounds__(128, 2) void gemm1_kernel(float* __restrict__ out)
{
    extern __shared__ uint32_t sm[];
    const uint32_t smb = (uint32_t)__cvta_generic_to_shared(sm);
    GEMM_DECLS
    const int m0 = blockIdx.x * BM;
    const int n0 = blockIdx.y * BN;
    GEMM_ISSUE(g_xt, g_wt, KC1)

    issue(0); issue(1);
    const int NK = HDIM / BK;   // 64
    for (int kt = 0; kt < NK; kt++) {
        if (kt + 1 < NK) cpa_wait1(); else cpa_wait0();
        __syncthreads();
        if (kt + 2 < NK) issue(kt + 2);
        GEMM_COMPUTE(kt)
    }

    // ---- epilogue ----
    __syncthreads();
    float* sf = (float*)sm;                    // [128][132]
    #pragma unroll
    for (int mt = 0; mt < 4; mt++) {
        #pragma unroll
        for (int nt = 0; nt < 8; nt++) {
            int r = wm * 64 + mt * 16 + g;
            int c = wn * 64 + nt * 8 + tg * 2;
            sf[r * 132 + c]           = acc[mt][nt][0];
            sf[r * 132 + c + 1]       = acc[mt][nt][1];
            sf[(r + 8) * 132 + c]     = acc[mt][nt][2];
            sf[(r + 8) * 132 + c + 1] = acc[mt][nt][3];
        }
    }
    __syncthreads();

    // raw logits, coalesced
    float* outL = out + OUT_LOGITS;
    for (int i = 0; i < 128; i++)
        outL[(size_t)(m0 + i) * VDIM + n0 + tid] = sf[i * 132 + tid];

    // probs in A-perm layout + z partial sums.
    // warp wid covers m16 tiles {2wid, 2wid+1}, all 16 v-chunks.
    float za[2][2] = {{0.f, 0.f}, {0.f, 0.f}};
    #pragma unroll 4
    for (int ft = 0; ft < 32; ft++) {
        int mt = ft >> 4;                     // local 0..1
        int vc = ft & 15;
        int r0 = (wid * 2 + mt) * 16 + g;
        float e0 = __expf(sf[r0 * 132 + vc * 8 + tg]);
        float e1 = __expf(sf[(r0 + 8) * 132 + vc * 8 + tg]);
        float e2 = __expf(sf[r0 * 132 + vc * 8 + tg + 4]);
        float e3 = __expf(sf[(r0 + 8) * 132 + vc * 8 + tg + 4]);
        za[mt][0] += e0 + e2;
        za[mt][1] += e1 + e3;
        uint4 o = { f2tf(e0), f2tf(e1), f2tf(e2), f2tf(e3) };
        *(uint4*)(g_probs + ((size_t)(m0 / 16 + wid * 2 + mt) * KC2
                             + n0 / 8 + vc) * 128 + lane * 4) = o;
    }
    float* zp = g_zpart + (size_t)blockIdx.y * BT + m0;
    #pragma unroll
    for (int mt = 0; mt < 2; mt++)
        #pragma unroll
        for (int h = 0; h < 2; h++) {
            float v = za[mt][h];
            v += __shfl_xor_sync(0xFFFFFFFFu, v, 1);
            v += __shfl_xor_sync(0xFFFFFFFFu, v, 2);
            if (tg == 0) zp[wid * 32 + mt * 16 + h * 8 + g] = v;
        }
}

// ---------------------------------------------------------------------------
// Phase 2: zred — Z, lse, 1/Z, ntl. Target dtype runtime-detected.
// ---------------------------------------------------------------------------
__global__ void zred_kernel(const void* __restrict__ target,
                            float* __restrict__ out)
{
    __shared__ int oddor;
    const int tid = threadIdx.x;
    const int lane = tid & 31;
    const int wid = tid >> 5;
    const int row = blockIdx.x * 8 + wid;

    if (tid == 0) oddor = 0;
    __syncthreads();
    {
        const int* t32 = (const int*)target;
        int f = 0;
        for (int i = tid; i < BT / 2; i += 256) f |= t32[2 * i + 1];
        if (f) atomicOr(&oddor, 1);
    }
    __syncthreads();

    float s = 0.f;
    for (int t = lane; t < NT1; t += 32)
        s += g_zpart[(size_t)t * BT + row];
    #pragma unroll
    for (int o = 16; o > 0; o >>= 1)
        s += __shfl_xor_sync(0xFFFFFFFFu, s, o);

    if (lane == 0) {
        out[OUT_LSE + row] = logf(s);
        g_scale[row] = 1.0f / s;
        long long t;
        if (oddor) t = (long long)((const int*)target)[row];
        else       t = ((const long long*)target)[row];
        if (t < 0) t = 0;
        if (t >= VDIM) t = VDIM - 1;
        out[OUT_NTL + row] = -out[OUT_LOGITS + (size_t)row * VDIM + t];
    }
}

__global__ void loss_kernel(float* __restrict__ out)
{
    __shared__ float red[256];
    const int tid = threadIdx.x;
    float s = 0.f;
    for (int i = tid; i < BT; i += 256)
        s += out[OUT_LSE + i] + out[OUT_NTL + i];
    red[tid] = s;
    __syncthreads();
    for (int st = 128; st > 0; st >>= 1) {
        if (tid < st) red[tid] += red[tid + st];
        __syncthreads();
    }
    if (tid == 0) out[OUT_LOSS] = red[0] / (float)BT;
}

// ---------------------------------------------------------------------------
// Phase 3: grad_x = diag(1/Z) * E @ w
// ---------------------------------------------------------------------------
__global__ __launch_bounds__(128, 2) void gemm2_kernel(float* __restrict__ out)
{
    extern __shared__ uint32_t sm[];
    const uint32_t smb = (uint32_t)__cvta_generic_to_shared(sm);
    GEMM_DECLS
    const int n0 = blockIdx.x * BN;
    const int m0 = blockIdx.y * BM;
    GEMM_ISSUE(g_probs, g_wt2, KC2)

    issue(0); issue(1);
    const int NK = VDIM / BK;   // 1000
    for (int kt = 0; kt < NK; kt++) {
        if (kt + 1 < NK) cpa_wait1(); else cpa_wait0();
        __syncthreads();
        if (kt + 2 < NK) issue(kt + 2);
        GEMM_COMPUTE(kt)
    }

    __syncthreads();
    float* sf = (float*)sm;
    #pragma unroll
    for (int mt = 0; mt < 4; mt++) {
        #pragma unroll
        for (int nt = 0; nt < 8; nt++) {
            int r = wm * 64 + mt * 16 + g;
            int c = wn * 64 + nt * 8 + tg * 2;
            sf[r * 132 + c]           = acc[mt][nt][0];
            sf[r * 132 + c + 1]       = acc[mt][nt][1];
            sf[(r + 8) * 132 + c]     = acc[mt][nt][2];
            sf[(r + 8) * 132 + c + 1] = acc[mt][nt][3];
        }
    }
    __syncthreads();
    float* outG = out + OUT_GRADX;
    for (int i = 0; i < 128; i++)
        outG[(size_t)(m0 + i) * HDIM + n0 + tid] = sf[i * 132 + tid] * g_scale[m0 + i];
}

// ---------------------------------------------------------------------------
extern "C" void kernel_launch(void* const* d_in, const int* in_sizes, int n_in,
                              void* d_out, int out_size)
{
    const float* x   = (const float*)d_in[0];
    const float* w   = (const float*)d_in[1];
    const void*  tgt = d_in[2];
    float*       out = (float*)d_out;

    cudaFuncSetAttribute(gemm1_kernel,
        cudaFuncAttributeMaxDynamicSharedMemorySize, G_SMEM);
    cudaFuncSetAttribute(gemm2_kernel,
        cudaFuncAttributeMaxDynamicSharedMemorySize, G_SMEM);

    convA_kernel <<<512,  128>>>(x);
    convB1_kernel<<<4096, 128>>>(w);
    convB2_kernel<<<4096, 128>>>(w);

    dim3 g1(BT / BM, VDIM / BN);   // (32, 250) m-fastest: x panels L2-resident
    gemm1_kernel<<<g1, 128, G_SMEM>>>(out);

    zred_kernel<<<BT / 8, 256>>>(tgt, out);
    loss_kernel<<<1, 256>>>(out);

    dim3 g2(HDIM / BN, BT / BM);   // (16, 32) n-fastest: probs rows shared in L2
    gemm2_kernel<<<g2, 128, G_SMEM>>>(out);
}

// round 7
// speedup vs baseline: 2.4882x; 1.0481x over previous
#include <cuda_runtime.h>
#include <cstdint>

#define BT   4096
#define HDIM 2048
#define VDIM 32000
#define NT1  (VDIM / 256)          // 125 gemm1 n-tiles
#define KC1  (HDIM / 8)            // 256 k-chunks gemm1
#define KC2  (VDIM / 8)            // 4000 k-chunks gemm2
#define SPLIT 4                    // gemm2 K-split

// Output layout: [loss(1) | logits(BT*V) | lse(BT) | ntl(BT) | grad_x(BT*H)]
#define OUT_LOSS   0
#define OUT_LOGITS 1LL
#define OUT_LSE    (1LL + (long long)BT * VDIM)
#define OUT_NTL    (OUT_LSE + BT)
#define OUT_GRADX  (OUT_NTL + BT)

// ---- gemm1: BM=128, BN=256, BK=64, 256 thr, 2 stages ----
#define G1_STG_W 24576             // A 8192 + B 16384 words
#define G1_SMEM (2 * G1_STG_W * 4) // 196608 B
// ---- gemm2: BM=128, BN=128, BK=32, 128 thr, 3 stages ----
#define G2_STG_W 8192
#define G2_SMEM (3 * G2_STG_W * 4) // 98304 B

// ---- scratch ----
// A-perm: [m16][k8][lane][4] : j0=(g,tg) j1=(g+8,tg) j2=(g,tg+4) j3=(g+8,tg+4)
// B-perm: [n8][k8][lane][2]  : j0=(n=g,k=tg) j1=(n=g,k=tg+4)
__device__ uint32_t g_xt   [(size_t)(BT / 16) * KC1 * 128];
__device__ uint32_t g_wt   [(size_t)(VDIM / 8) * KC1 * 64];   // (n=v,k=h)
__device__ uint32_t g_wt2  [(size_t)(HDIM / 8) * KC2 * 64];   // (n=h,k=v)
__device__ uint32_t g_probs[(size_t)(BT / 16) * KC2 * 128];
__device__ float    g_gpart[(size_t)SPLIT * BT * HDIM];
__device__ float    g_zpart[(size_t)NT1 * BT];
__device__ float    g_scale[BT];

__device__ __forceinline__ uint32_t f2tf(float x) {
    uint32_t r;
    asm("cvt.rna.tf32.f32 %0, %1;" : "=r"(r) : "f"(x));
    return r;
}
__device__ __forceinline__ void mma8(float* d, const uint32_t* a, const uint32_t* b) {
    asm volatile(
        "mma.sync.aligned.m16n8k8.row.col.f32.tf32.tf32.f32 "
        "{%0,%1,%2,%3}, {%4,%5,%6,%7}, {%8,%9}, {%0,%1,%2,%3};\n"
        : "+f"(d[0]), "+f"(d[1]), "+f"(d[2]), "+f"(d[3])
        : "r"(a[0]), "r"(a[1]), "r"(a[2]), "r"(a[3]),
          "r"(b[0]), "r"(b[1]));
}
__device__ __forceinline__ void cpa16(uint32_t smem, const void* gmem) {
    asm volatile("cp.async.cg.shared.global [%0], [%1], 16;\n" :: "r"(smem), "l"(gmem));
}
__device__ __forceinline__ void cpa_commit() {
    asm volatile("cp.async.commit_group;\n" ::: "memory");
}
__device__ __forceinline__ void cpa_wait0() {
    asm volatile("cp.async.wait_group 0;\n" ::: "memory");
}
__device__ __forceinline__ void cpa_wait1() {
    asm volatile("cp.async.wait_group 1;\n" ::: "memory");
}

// ---------------------------------------------------------------------------
// Converters into fragment-major layouts
// ---------------------------------------------------------------------------
__global__ void convA_kernel(const float* __restrict__ x)
{
    const int lane = threadIdx.x & 31;
    const int g = lane >> 2, tg = lane & 3;
    const int warp = (blockIdx.x * blockDim.x + threadIdx.x) >> 5;
    const int nwarp = (gridDim.x * blockDim.x) >> 5;
    const int NF = (BT / 16) * KC1;
    for (int f = warp; f < NF; f += nwarp) {
        int m16 = f >> 8, kc = f & (KC1 - 1);
        const float* p = x + (size_t)(m16 * 16 + g) * HDIM + kc * 8 + tg;
        uint4 o = { f2tf(p[0]), f2tf(p[8 * HDIM]), f2tf(p[4]), f2tf(p[8 * HDIM + 4]) };
        *(uint4*)(g_xt + (size_t)f * 128 + lane * 4) = o;
    }
}
__global__ void convB1_kernel(const float* __restrict__ w)
{
    const int lane = threadIdx.x & 31;
    const int g = lane >> 2, tg = lane & 3;
    const int warp = (blockIdx.x * blockDim.x + threadIdx.x) >> 5;
    const int nwarp = (gridDim.x * blockDim.x) >> 5;
    const int NF = (VDIM / 8) * KC1;
    for (int f = warp; f < NF; f += nwarp) {
        int v8 = f >> 8, kc = f & (KC1 - 1);
        const float* p = w + (size_t)(v8 * 8 + g) * HDIM + kc * 8 + tg;
        uint2 o = { f2tf(p[0]), f2tf(p[4]) };
        *(uint2*)(g_wt + (size_t)f * 64 + lane * 2) = o;
    }
}
__global__ void convB2_kernel(const float* __restrict__ w)
{
    const int lane = threadIdx.x & 31;
    const int g = lane >> 2, tg = lane & 3;
    const int warp = (blockIdx.x * blockDim.x + threadIdx.x) >> 5;
    const int nwarp = (gridDim.x * blockDim.x) >> 5;
    const int NF = (HDIM / 8) * KC2;
    for (int f = warp; f < NF; f += nwarp) {
        int h8 = f / KC2, vc = f - h8 * KC2;
        const float* p = w + (size_t)(vc * 8 + tg) * HDIM + h8 * 8 + g;
        uint2 o = { f2tf(p[0]), f2tf(p[4 * HDIM]) };
        *(uint2*)(g_wt2 + (size_t)f * 64 + lane * 2) = o;
    }
}

// ---------------------------------------------------------------------------
// Phase 1: logits = x @ w^T.  128x256 tile, BK=64, 8 warps (2m x 4n), 64x64 warp.
// Epilogue: logits, probs (A-perm), z partials.
// ---------------------------------------------------------------------------
__global__ __launch_bounds__(256, 1) void gemm1_kernel(float* __restrict__ out)
{
    extern __shared__ uint32_t sm[];
    const uint32_t smb = (uint32_t)__cvta_generic_to_shared(sm);
    const int tid  = threadIdx.x;
    const int lane = tid & 31;
    const int wid  = tid >> 5;
    const int g    = lane >> 2;
    const int tg   = lane & 3;
    const int wm   = wid & 1;      // 2 warps along M
    const int wn   = wid >> 1;     // 4 warps along N
    const int m0   = blockIdx.x * 128;
    const int n0   = blockIdx.y * 256;

    float acc[4][8][4];
    #pragma unroll
    for (int i = 0; i < 4; i++)
        #pragma unroll
        for (int j = 0; j < 8; j++)
            #pragma unroll
            for (int q = 0; q < 4; q++) acc[i][j][q] = 0.f;

    auto issue = [&](int kt) {
        const uint32_t sb = smb + (uint32_t)(kt & 1) * (G1_STG_W * 4);
        const int kc0 = kt * 8;
        #pragma unroll
        for (int i = 0; i < 8; i++) {               // A: 2048 chunks
            int q = tid + i * 256;
            int ai = q >> 8, kcl = (q >> 5) & 7, c = q & 31;
            cpa16(sb + (ai * 1024 + kcl * 128 + c * 4) * 4,
                  g_xt + ((size_t)(m0 / 16 + ai) * KC1 + kc0 + kcl) * 128 + c * 4);
        }
        #pragma unroll
        for (int i = 0; i < 16; i++) {              // B: 4096 chunks
            int q = tid + i * 256;
            int bj = q >> 7, kcl = (q >> 4) & 7, c = q & 15;
            cpa16(sb + (8192 + bj * 512 + kcl * 64 + c * 4) * 4,
                  g_wt + ((size_t)(n0 / 8 + bj) * KC1 + kc0 + kcl) * 64 + c * 4);
        }
        cpa_commit();
    };

    issue(0);
    const int NK = HDIM / 64;   // 32
    for (int kt = 0; kt < NK; kt++) {
        __syncthreads();                   // prev compute done before overwrite
        if (kt + 1 < NK) { issue(kt + 1); cpa_wait1(); }
        else             { cpa_wait0(); }
        __syncthreads();                   // stage kt visible to all warps

        const uint32_t* Aw = sm + (kt & 1) * G1_STG_W;
        const uint32_t* Bw = Aw + 8192;
        #pragma unroll
        for (int kc = 0; kc < 8; kc++) {
            uint4 av[4];
            #pragma unroll
            for (int mt = 0; mt < 4; mt++)
                av[mt] = *(const uint4*)(Aw + (wm * 4 + mt) * 1024 + kc * 128 + lane * 4);
            #pragma unroll
            for (int nt = 0; nt < 8; nt++) {
                uint2 bv = *(const uint2*)(Bw + (wn * 8 + nt) * 512 + kc * 64 + lane * 2);
                #pragma unroll
                for (int mt = 0; mt < 4; mt++)
                    mma8(acc[mt][nt], (const uint32_t*)&av[mt], (const uint32_t*)&bv);
            }
        }
    }

    // ---- epilogue ----
    __syncthreads();
    float* sf = (float*)sm;                // [128][260], 133 KB
    #pragma unroll
    for (int mt = 0; mt < 4; mt++) {
        #pragma unroll
        for (int nt = 0; nt < 8; nt++) {
            int r = wm * 64 + mt * 16 + g;
            int c = wn * 64 + nt * 8 + tg * 2;
            sf[r * 260 + c]           = acc[mt][nt][0];
            sf[r * 260 + c + 1]       = acc[mt][nt][1];
            sf[(r + 8) * 260 + c]     = acc[mt][nt][2];
            sf[(r + 8) * 260 + c + 1] = acc[mt][nt][3];
        }
    }
    __syncthreads();

    float* outL = out + OUT_LOGITS;
    for (int i = 0; i < 128; i++)
        outL[(size_t)(m0 + i) * VDIM + n0 + tid] = sf[i * 260 + tid];

    // probs (A-perm) + z partials: warp wid owns m16 tile wid, 32 v-chunks
    float za[2] = {0.f, 0.f};
    const int r0 = wid * 16 + g;
    #pragma unroll 4
    for (int vc = 0; vc < 32; vc++) {
        float e0 = __expf(sf[r0 * 260 + vc * 8 + tg]);
        float e1 = __expf(sf[(r0 + 8) * 260 + vc * 8 + tg]);
        float e2 = __expf(sf[r0 * 260 + vc * 8 + tg + 4]);
        float e3 = __expf(sf[(r0 + 8) * 260 + vc * 8 + tg + 4]);
        za[0] += e0 + e2;
        za[1] += e1 + e3;
        uint4 o = { f2tf(e0), f2tf(e1), f2tf(e2), f2tf(e3) };
        *(uint4*)(g_probs + ((size_t)(m0 / 16 + wid) * KC2 + n0 / 8 + vc) * 128
                  + lane * 4) = o;
    }
    float* zp = g_zpart + (size_t)blockIdx.y * BT + m0;
    #pragma unroll
    for (int h = 0; h < 2; h++) {
        float v = za[h];
        v += __shfl_xor_sync(0xFFFFFFFFu, v, 1);
        v += __shfl_xor_sync(0xFFFFFFFFu, v, 2);
        if (tg == 0) zp[wid * 16 + h * 8 + g] = v;
    }
}

// ---------------------------------------------------------------------------
// Phase 2: zred — Z, lse, 1/Z, ntl. Target dtype runtime-detected
// (JAX x64-off downcasts int64 -> int32; odd words all-zero => int64).
// ---------------------------------------------------------------------------
__global__ void zred_kernel(const void* __restrict__ target,
                            float* __restrict__ out)
{
    __shared__ int oddor;
    const int tid = threadIdx.x;
    const int lane = tid & 31;
    const int wid = tid >> 5;
    const int row = blockIdx.x * 8 + wid;

    if (tid == 0) oddor = 0;
    __syncthreads();
    {
        const int* t32 = (const int*)target;
        int f = 0;
        for (int i = tid; i < BT / 2; i += 256) f |= t32[2 * i + 1];
        if (f) atomicOr(&oddor, 1);
    }
    __syncthreads();

    float s = 0.f;
    for (int t = lane; t < NT1; t += 32)
        s += g_zpart[(size_t)t * BT + row];
    #pragma unroll
    for (int o = 16; o > 0; o >>= 1)
        s += __shfl_xor_sync(0xFFFFFFFFu, s, o);

    if (lane == 0) {
        out[OUT_LSE + row] = logf(s);
        g_scale[row] = 1.0f / s;
        long long t;
        if (oddor) t = (long long)((const int*)target)[row];
        else       t = ((const long long*)target)[row];
        if (t < 0) t = 0;
        if (t >= VDIM) t = VDIM - 1;
        out[OUT_NTL + row] = -out[OUT_LOGITS + (size_t)row * VDIM + t];
    }
}

__global__ void loss_kernel(float* __restrict__ out)
{
    __shared__ float red[256];
    const int tid = threadIdx.x;
    float s = 0.f;
    for (int i = tid; i < BT; i += 256)
        s += out[OUT_LSE + i] + out[OUT_NTL + i];
    red[tid] = s;
    __syncthreads();
    for (int st = 128; st > 0; st >>= 1) {
        if (tid < st) red[tid] += red[tid + st];
        __syncthreads();
    }
    if (tid == 0) out[OUT_LOSS] = red[0] / (float)BT;
}

// ---------------------------------------------------------------------------
// Phase 3: grad partials = E @ w, K-split x4 (BM=128,BN=128,BK=32,128 thr)
// ---------------------------------------------------------------------------
__global__ __launch_bounds__(128, 2) void gemm2_kernel()
{
    extern __shared__ uint32_t sm[];
    const uint32_t smb = (uint32_t)__cvta_generic_to_shared(sm);
    const int tid  = threadIdx.x;
    const int lane = tid & 31;
    const int wid  = tid >> 5;
    const int wm   = wid & 1;
    const int wn   = wid >> 1;
    const int n0   = blockIdx.x * 128;
    const int m0   = blockIdx.y * 128;
    const int s    = blockIdx.z;

    float acc[4][8][4];
    #pragma unroll
    for (int i = 0; i < 4; i++)
        #pragma unroll
        for (int j = 0; j < 8; j++)
            #pragma unroll
            for (int q = 0; q < 4; q++) acc[i][j][q] = 0.f;

    auto issue = [&](int kt) {
        const uint32_t sb = smb + (uint32_t)(kt % 3) * (G2_STG_W * 4);
        const int kc0 = kt * 4;
        #pragma unroll
        for (int i = 0; i < 8; i++)
            cpa16(sb + i * 2048 + tid * 16,
                  g_probs + ((size_t)(m0 / 16 + i) * KC2 + kc0) * 128 + tid * 4);
        #pragma unroll
        for (int i = 0; i < 8; i++) {
            int q = tid + i * 128;
            int n8 = q >> 6, off = q & 63;
            cpa16(sb + 16384 + q * 16,
                  g_wt2 + ((size_t)(n0 / 8 + n8) * KC2 + kc0) * 64 + off * 4);
        }
        cpa_commit();
    };

    const int kbase = s * (VDIM / 32 / SPLIT);       // 250 iters per split
    const int kend  = kbase + (VDIM / 32 / SPLIT);
    issue(kbase); issue(kbase + 1);
    for (int kt = kbase; kt < kend; kt++) {
        if (kt + 1 < kend) cpa_wait1(); else cpa_wait0();
        __syncthreads();
        if (kt + 2 < kend) issue(kt + 2);
        const uint32_t* Aw = sm + (kt % 3) * G2_STG_W;
        const uint32_t* Bw = Aw + 4096;
        #pragma unroll
        for (int kc = 0; kc < 4; kc++) {
            uint4 av[4];
            #pragma unroll
            for (int mt = 0; mt < 4; mt++)
                av[mt] = *(const uint4*)(Aw + (wm * 4 + mt) * 512 + kc * 128 + lane * 4);
            #pragma unroll
            for (int nt = 0; nt < 8; nt++) {
                uint2 bv = *(const uint2*)(Bw + (wn * 8 + nt) * 256 + kc * 64 + lane * 2);
                #pragma unroll
                for (int mt = 0; mt < 4; mt++)
                    mma8(acc[mt][nt], (const uint32_t*)&av[mt], (const uint32_t*)&bv);
            }
        }
    }

    __syncthreads();
    float* sf = (float*)sm;                // [128][132]
    const int g = lane >> 2, tg = lane & 3;
    #pragma unroll
    for (int mt = 0; mt < 4; mt++) {
        #pragma unroll
        for (int nt = 0; nt < 8; nt++) {
            int r = wm * 64 + mt * 16 + g;
            int c = wn * 64 + nt * 8 + tg * 2;
            sf[r * 132 + c]           = acc[mt][nt][0];
            sf[r * 132 + c + 1]       = acc[mt][nt][1];
            sf[(r + 8) * 132 + c]     = acc[mt][nt][2];
            sf[(r + 8) * 132 + c + 1] = acc[mt][nt][3];
        }
    }
    __syncthreads();
    float* gp = g_gpart + (size_t)s * BT * HDIM;
    for (int i = 0; i < 128; i++)
        gp[(size_t)(m0 + i) * HDIM + n0 + tid] = sf[i * 132 + tid];
}

// ---------------------------------------------------------------------------
// Phase 4: grad_x = (sum_s partial) * 1/Z
// ---------------------------------------------------------------------------
__global__ void gradred_kernel(float* __restrict__ out)
{
    const int row = blockIdx.x;
    const float sc = g_scale[row];
    float* o = out + OUT_GRADX + (size_t)row * HDIM;
    const float* p = g_gpart + (size_t)row * HDIM;
    for (int c = threadIdx.x; c < HDIM; c += 256) {
        float v = p[c];
        #pragma unroll
        for (int s = 1; s < SPLIT; s++)
            v += p[(size_t)s * BT * HDIM + c];
        o[c] = v * sc;
    }
}

// ---------------------------------------------------------------------------
extern "C" void kernel_launch(void* const* d_in, const int* in_sizes, int n_in,
                              void* d_out, int out_size)
{
    const float* x   = (const float*)d_in[0];
    const float* w   = (const float*)d_in[1];
    const void*  tgt = d_in[2];
    float*       out = (float*)d_out;

    cudaFuncSetAttribute(gemm1_kernel,
        cudaFuncAttributeMaxDynamicSharedMemorySize, G1_SMEM);
    cudaFuncSetAttribute(gemm2_kernel,
        cudaFuncAttributeMaxDynamicSharedMemorySize, G2_SMEM);

    convA_kernel <<<512,  128>>>(x);
    convB1_kernel<<<4096, 128>>>(w);
    convB2_kernel<<<4096, 128>>>(w);

    dim3 g1(BT / 128, VDIM / 256);      // (32, 125) m-fastest
    gemm1_kernel<<<g1, 256, G1_SMEM>>>(out);

    zred_kernel<<<BT / 8, 256>>>(tgt, out);
    loss_kernel<<<1, 256>>>(out);

    dim3 g2(HDIM / 128, BT / 128, SPLIT);  // (16, 32, 4) = 2048 CTAs
    gemm2_kernel<<<g2, 128, G2_SMEM>>>();
    gradred_kernel<<<BT, 256>>>(out);
}